// round 12
// baseline (speedup 1.0000x reference)
#include <cuda_runtime.h>
#include <cuda_bf16.h>
#include <cstdint>
#include <cstddef>

#define DK 256        // feature dim
#define NC 32         // nodes per chunk (GEMM2 K)
#define ZS 74         // split-K CTAs per d-tile (x4 d-tiles = 296 CTAs, 2/SM)

// ---- smem layout (per CTA ~107.5 KB so 2 CTAs fit per SM) ----
#define W_STRIDE   528                     // 256 bf16 + 8 pad
#define ND_STRIDE  528
#define MKB_STRIDE 80                      // 32 bf16 + 8 pad (mask, bf16)
#define YT_STRIDE  80                      // 32 bf16 + 8 pad
#define OFF_WT  0                          // 64 x 528 = 33792
#define OFF_WG  33792
#define OFF_ND  67584                      // 32 x 528 = 16896
#define OFF_MK  84480                      // 256 x 80 = 20480
#define OFF_YT  104960                     // 64 x 80  = 5120
#define SMEM_TOTAL 110080

static __device__ __forceinline__ uint32_t smem_u32(const void* p) {
    uint32_t a;
    asm("{ .reg .u64 t; cvta.to.shared.u64 t, %1; cvt.u32.u64 %0, t; }" : "=r"(a) : "l"(p));
    return a;
}

#define LDSM_X4(R, addr)                                                      \
    asm volatile("ldmatrix.sync.aligned.m8n8.x4.shared.b16 {%0,%1,%2,%3}, [%4];" \
                 : "=r"((R)[0]), "=r"((R)[1]), "=r"((R)[2]), "=r"((R)[3])     \
                 : "r"(addr))

#define MMA_BF16(C, A, b0, b1)                                                \
    asm volatile("mma.sync.aligned.m16n8k16.row.col.f32.bf16.bf16.f32 "       \
                 "{%0,%1,%2,%3},{%4,%5,%6,%7},{%8,%9},{%0,%1,%2,%3};"         \
                 : "+f"((C)[0]), "+f"((C)[1]), "+f"((C)[2]), "+f"((C)[3])     \
                 : "r"((A)[0]), "r"((A)[1]), "r"((A)[2]), "r"((A)[3]),        \
                   "r"(b0), "r"(b1))

// mask int {0,1} pair -> packed bf16x2 {1.0 or 0.0}: exact, 2 IMADs
static __device__ __forceinline__ uint32_t cvtm(int x, int y) {
    return (uint32_t)x * 0x3F80u + (uint32_t)y * 0x3F800000u;
}

static __device__ __forceinline__ uint2 pack_bf4(float4 v) {
    __nv_bfloat162 lo = __floats2bfloat162_rn(v.x, v.y);
    __nv_bfloat162 hi = __floats2bfloat162_rn(v.z, v.w);
    uint2 u;
    u.x = *reinterpret_cast<uint32_t*>(&lo);
    u.y = *reinterpret_cast<uint32_t*>(&hi);
    return u;
}

static __device__ __forceinline__ float sigm(float x) { return 1.0f / (1.0f + __expf(-x)); }

// ---------------------------------------------------------------------------
// 2-CTA/SM fused kernel (grid 74 z x 4 d-tiles, 256 thr):
// per chunk of 32 nodes:
//   stage nodes(f32->bf16) + mask(int->bf16) | bar
//   GEMM1 (4m x 2n, warp 16d x 16n): yT[64d x 32n] = W @ nodes^T (x2 mat)
//   gate epilogue -> yT bf16 | bar
//   GEMM2 (8m x 1n, warp 32b x 64d): acc2 += mask @ yT | bar
// Exposed staging latency is covered by the sibling CTA on the same SM.
// Persistent regs: acc2 (64) only. Final atomicAdd drain.
// ---------------------------------------------------------------------------
__global__ __launch_bounds__(256, 2)
void fused_agg(const float* __restrict__ nodes, const int* __restrict__ mask,
               const float* __restrict__ Wt, const float* __restrict__ bt,
               const float* __restrict__ Wg, const float* __restrict__ bg,
               float* __restrict__ out, int Nn)
{
    extern __shared__ char sm[];
    const uint32_t sb = smem_u32(sm);
    const int tid  = threadIdx.x;
    const int lane = tid & 31;
    const int wid  = tid >> 5;          // 0..7
    const int g    = lane >> 2;
    const int tg   = lane & 3;
    const int z    = blockIdx.x;        // 0..73
    const int d0   = blockIdx.y * 64;   // 0..3 -> d window

    // GEMM1 warp roles: 4 m-warps (16 d rows) x 2 n-warps (16 n cols)
    const int wm1 = wid & 3;
    const int wn1 = wid >> 2;

    const float bt0 = bt[d0 + wm1 * 16 + g];
    const float bt1 = bt[d0 + wm1 * 16 + 8 + g];
    const float bg0 = bg[d0 + wm1 * 16 + g];
    const float bg1 = bg[d0 + wm1 * 16 + 8 + g];

    // Persistent GEMM2 accumulators: 2 mf x 8 n8 x 4 = 64 regs
    float acc2[2][8][4];
    #pragma unroll
    for (int i = 0; i < 2; i++)
        #pragma unroll
        for (int j = 0; j < 8; j++)
            #pragma unroll
            for (int q = 0; q < 4; q++) acc2[i][j][q] = 0.f;

    const int NCHK = Nn / NC;   // 200000/32 = 6250 exactly

    // ---- stage resident W (64 d x 256 k, both matrices, f32 -> bf16) ----
    #pragma unroll
    for (int i = 0; i < 16; i++) {
        int f4  = tid + i * 256;            // 4096 float4 per matrix
        int row = f4 >> 6;                  // 0..63
        int col = (f4 & 63) * 4;
        uint2 a = pack_bf4(*(const float4*)(Wt + (size_t)(d0 + row) * DK + col));
        uint2 b = pack_bf4(*(const float4*)(Wg + (size_t)(d0 + row) * DK + col));
        *(uint2*)(sm + OFF_WT + row * W_STRIDE + col * 2) = a;
        *(uint2*)(sm + OFF_WG + row * W_STRIDE + col * 2) = b;
    }

    // ldmatrix lane addresses
    const uint32_t aWt = sb + OFF_WT + (wm1 * 16 + (lane & 15)) * W_STRIDE + ((lane >> 4) << 4);
    const uint32_t aWg = aWt + (uint32_t)(OFF_WG - OFF_WT);
    const uint32_t bNd = sb + OFF_ND
                       + (wn1 * 16 + (lane & 7) + ((lane >> 4) << 3)) * ND_STRIDE
                       + (((lane >> 3) & 1) << 4);
    const uint32_t aMK = sb + OFF_MK + (wid * 32 + (lane & 15)) * MKB_STRIDE + ((lane >> 4) << 4);
    const uint32_t bYT = sb + OFF_YT
                       + ((lane & 7) + ((lane >> 4) << 3)) * YT_STRIDE
                       + (((lane >> 3) & 1) << 4);

    // staging maps
    const int srow = tid >> 3;              // nodes: 0..31 rows, 8 thr/row
    const int sc8  = tid & 7;               // 8 float4 per thread, strided

    for (int c = z; c < NCHK; c += ZS) {
        const int n0 = c * NC;

        // ---- stage nodes [32 x 256] f32->bf16 ----
        {
            const float* src = nodes + (size_t)(n0 + srow) * DK + sc8 * 4;
            char* dst = sm + OFF_ND + srow * ND_STRIDE + sc8 * 8;
            #pragma unroll
            for (int i = 0; i < 8; i++)
                *(uint2*)(dst + i * 64) = pack_bf4(*(const float4*)(src + i * 32));
        }
        // ---- stage mask [256 x 32] int->bf16 (1 thread per row) ----
        {
            const int* mp = mask + (size_t)tid * Nn + n0;
            char* dm = sm + OFF_MK + tid * MKB_STRIDE;
            #pragma unroll
            for (int j = 0; j < 4; j++) {
                int4 v0 = *(const int4*)(mp + j * 8);
                int4 v1 = *(const int4*)(mp + j * 8 + 4);
                *(uint4*)(dm + j * 16) = make_uint4(cvtm(v0.x, v0.y), cvtm(v0.z, v0.w),
                                                    cvtm(v1.x, v1.y), cvtm(v1.z, v1.w));
            }
        }
        __syncthreads();   // nodes + mask (+W on iter 0) visible

        // ---- GEMM1: yT = W @ nodes^T  (M=64, N=32, K=256) ----
        float aT0[4] = {0,0,0,0}, aT1[4] = {0,0,0,0};
        float aG0[4] = {0,0,0,0}, aG1[4] = {0,0,0,0};
        #pragma unroll
        for (int ks = 0; ks < 16; ks++) {
            uint32_t At[4], Ag[4], Bn[4];
            LDSM_X4(At, aWt + ks * 32);
            LDSM_X4(Ag, aWg + ks * 32);
            LDSM_X4(Bn, bNd + ks * 32);
            MMA_BF16(aT0, At, Bn[0], Bn[1]);
            MMA_BF16(aT1, At, Bn[2], Bn[3]);
            MMA_BF16(aG0, Ag, Bn[0], Bn[1]);
            MMA_BF16(aG1, Ag, Bn[2], Bn[3]);
        }

        // ---- epilogue: y = (t+bt)*sigmoid(g+bg) -> yT smem bf16 ----
        {
            char* r0 = sm + OFF_YT + (wm1 * 16 + g) * YT_STRIDE + (wn1 * 16 + 2 * tg) * 2;
            char* r1 = r0 + 8 * YT_STRIDE;
            __nv_bfloat162 h;
            h = __floats2bfloat162_rn((aT0[0] + bt0) * sigm(aG0[0] + bg0),
                                      (aT0[1] + bt0) * sigm(aG0[1] + bg0));
            *(uint32_t*)r0 = *reinterpret_cast<uint32_t*>(&h);
            h = __floats2bfloat162_rn((aT0[2] + bt1) * sigm(aG0[2] + bg1),
                                      (aT0[3] + bt1) * sigm(aG0[3] + bg1));
            *(uint32_t*)r1 = *reinterpret_cast<uint32_t*>(&h);
            h = __floats2bfloat162_rn((aT1[0] + bt0) * sigm(aG1[0] + bg0),
                                      (aT1[1] + bt0) * sigm(aG1[1] + bg0));
            *(uint32_t*)(r0 + 16) = *reinterpret_cast<uint32_t*>(&h);
            h = __floats2bfloat162_rn((aT1[2] + bt1) * sigm(aG1[2] + bg1),
                                      (aT1[3] + bt1) * sigm(aG1[3] + bg1));
            *(uint32_t*)(r1 + 16) = *reinterpret_cast<uint32_t*>(&h);
        }
        __syncthreads();   // yT visible

        // ---- GEMM2: acc2 += mask @ yT  (warp 32b x 64d, K=32) ----
        #pragma unroll
        for (int ks = 0; ks < 2; ks++) {
            uint32_t A0[4], A1[4];
            LDSM_X4(A0, aMK + ks * 32);
            LDSM_X4(A1, aMK + 16 * MKB_STRIDE + ks * 32);
            #pragma unroll
            for (int nf = 0; nf < 4; nf++) {
                uint32_t Y[4];
                LDSM_X4(Y, bYT + nf * 16 * YT_STRIDE + ks * 32);
                MMA_BF16(acc2[0][2 * nf],     A0, Y[0], Y[1]);
                MMA_BF16(acc2[0][2 * nf + 1], A0, Y[2], Y[3]);
                MMA_BF16(acc2[1][2 * nf],     A1, Y[0], Y[1]);
                MMA_BF16(acc2[1][2 * nf + 1], A1, Y[2], Y[3]);
            }
        }
        __syncthreads();   // GEMM2 done: nodes/mask/yT smem free
    }

    // ---- drain: atomic-accumulate split-K partials ----
    #pragma unroll
    for (int mf = 0; mf < 2; mf++) {
        const int r = wid * 32 + mf * 16 + g;
        #pragma unroll
        for (int j = 0; j < 8; j++) {
            const int cb = d0 + j * 8 + 2 * tg;
            atomicAdd(out + (size_t)r * DK + cb,           acc2[mf][j][0]);
            atomicAdd(out + (size_t)r * DK + cb + 1,       acc2[mf][j][1]);
            atomicAdd(out + (size_t)(r + 8) * DK + cb,     acc2[mf][j][2]);
            atomicAdd(out + (size_t)(r + 8) * DK + cb + 1, acc2[mf][j][3]);
        }
    }
}

__global__ void kzero(float* __restrict__ o, int n) {
    const int i = blockIdx.x * 256 + threadIdx.x;
    if (i < n) o[i] = 0.f;
}

extern "C" void kernel_launch(void* const* d_in, const int* in_sizes, int n_in,
                              void* d_out, int out_size)
{
    const float* nodes = (const float*)d_in[0];
    const int*   mask  = (const int*)  d_in[1];
    const float* Wt    = (const float*)d_in[2];
    const float* bt    = (const float*)d_in[3];
    const float* Wg    = (const float*)d_in[4];
    const float* bg    = (const float*)d_in[5];
    float* out = (float*)d_out;

    const int Nn = in_sizes[0] / DK;   // 200000

    cudaFuncSetAttribute(fused_agg, cudaFuncAttributeMaxDynamicSharedMemorySize, SMEM_TOTAL);

    kzero<<<(out_size + 255) / 256, 256>>>(out, out_size);
    fused_agg<<<dim3(ZS, 4), 256, SMEM_TOTAL>>>(nodes, mask, Wt, bt, Wg, bg, out, Nn);
}

// round 13
// speedup vs baseline: 1.0534x; 1.0534x over previous
#include <cuda_runtime.h>
#include <cuda_bf16.h>
#include <cstdint>
#include <cstddef>

#define DK 256        // feature dim
#define NC 64         // nodes per chunk (GEMM2 K)
#define ZS 74         // split-K CTAs per d-tile (x2 d-tiles = 148 CTAs)

// ---- smem layout ----
#define W_STRIDE  528                      // 256 bf16 + 8 pad
#define ND_STRIDE 528
#define MK_STRIDE 144                      // 64 bf16 + 8 pad (mask, bf16)
#define YT_STRIDE 144                      // 64 bf16 + 8 pad
#define OFF_WT 0                           // 128 x 528 x2 matrices
#define OFF_WG 67584
#define OFF_ND 135168                      // 64 x 528  = 33792
#define OFF_MK 168960                      // 256 x 144 = 36864
#define OFF_YT 205824                      // 128 x 144 = 18432
#define SMEM_TOTAL 224256

static __device__ __forceinline__ uint32_t smem_u32(const void* p) {
    uint32_t a;
    asm("{ .reg .u64 t; cvta.to.shared.u64 t, %1; cvt.u32.u64 %0, t; }" : "=r"(a) : "l"(p));
    return a;
}

#define LDSM_X4(R, addr)                                                      \
    asm volatile("ldmatrix.sync.aligned.m8n8.x4.shared.b16 {%0,%1,%2,%3}, [%4];" \
                 : "=r"((R)[0]), "=r"((R)[1]), "=r"((R)[2]), "=r"((R)[3])     \
                 : "r"(addr))

#define MMA_BF16(C, A, b0, b1)                                                \
    asm volatile("mma.sync.aligned.m16n8k16.row.col.f32.bf16.bf16.f32 "       \
                 "{%0,%1,%2,%3},{%4,%5,%6,%7},{%8,%9},{%0,%1,%2,%3};"         \
                 : "+f"((C)[0]), "+f"((C)[1]), "+f"((C)[2]), "+f"((C)[3])     \
                 : "r"((A)[0]), "r"((A)[1]), "r"((A)[2]), "r"((A)[3]),        \
                   "r"(b0), "r"(b1))

// mask int {0,1} pair -> packed bf16x2 {1.0 or 0.0}: exact, 2 IMADs
static __device__ __forceinline__ uint32_t cvtm(int x, int y) {
    return (uint32_t)x * 0x3F80u + (uint32_t)y * 0x3F800000u;
}

static __device__ __forceinline__ uint2 pack_bf4(float4 v) {
    __nv_bfloat162 lo = __floats2bfloat162_rn(v.x, v.y);
    __nv_bfloat162 hi = __floats2bfloat162_rn(v.z, v.w);
    uint2 u;
    u.x = *reinterpret_cast<uint32_t*>(&lo);
    u.y = *reinterpret_cast<uint32_t*>(&hi);
    return u;
}

static __device__ __forceinline__ float sigm(float x) { return 1.0f / (1.0f + __expf(-x)); }

// ---------------------------------------------------------------------------
// R8 structure with 64-node chunks (grid 74 z x 2 d-tiles, 512 thr):
//  STS nodes+mask(c) | bar | GEMM1 (8m x 2n, warp 16d x 32n, K=256) |
//  epilogue -> yT bf16 | prefetch(c+ZS) regs | bar | GEMM2 (warp 16b x 128d,
//  K=64, A via ldmatrix from bf16 mask tile) | bar
// ---------------------------------------------------------------------------
__global__ __launch_bounds__(512, 1)
void fused_agg(const float* __restrict__ nodes, const int* __restrict__ mask,
               const float* __restrict__ Wt, const float* __restrict__ bt,
               const float* __restrict__ Wg, const float* __restrict__ bg,
               float* __restrict__ out, int Nn)
{
    extern __shared__ char sm[];
    const uint32_t sb = smem_u32(sm);
    const int tid  = threadIdx.x;
    const int lane = tid & 31;
    const int wid  = tid >> 5;
    const int g    = lane >> 2;
    const int tg   = lane & 3;
    const int z    = blockIdx.x;
    const int d0   = blockIdx.y * 128;

    // GEMM1 warp roles: 8 m-warps (16 d rows) x 2 n-warps (32 n cols)
    const int wm = wid & 7;
    const int wn = wid >> 3;

    const float bt0 = bt[d0 + wm * 16 + g];
    const float bt1 = bt[d0 + wm * 16 + 8 + g];
    const float bg0 = bg[d0 + wm * 16 + g];
    const float bg1 = bg[d0 + wm * 16 + 8 + g];

    // Persistent GEMM2 accumulators: warp tile 16b x 128d = 16 n8 x 4 regs
    float acc2[16][4];
    #pragma unroll
    for (int j = 0; j < 16; j++)
        #pragma unroll
        for (int q = 0; q < 4; q++) acc2[j][q] = 0.f;

    const int NCHK = Nn / NC;   // 200000/64 = 3125 exactly

    // ---- stage resident W (128 d x 256 k, both matrices, f32 -> bf16) ----
    #pragma unroll
    for (int i = 0; i < 16; i++) {
        int f4  = tid + i * 512;
        int row = f4 >> 6;
        int col = (f4 & 63) * 4;
        uint2 a = pack_bf4(*(const float4*)(Wt + (size_t)(d0 + row) * DK + col));
        uint2 b = pack_bf4(*(const float4*)(Wg + (size_t)(d0 + row) * DK + col));
        *(uint2*)(sm + OFF_WT + row * W_STRIDE + col * 2) = a;
        *(uint2*)(sm + OFF_WG + row * W_STRIDE + col * 2) = b;
    }

    // ldmatrix lane addresses
    const uint32_t aWt = sb + OFF_WT + (wm * 16 + (lane & 15)) * W_STRIDE + ((lane >> 4) << 4);
    const uint32_t aWg = aWt + (uint32_t)(OFF_WG - OFF_WT);
    const uint32_t bNd = sb + OFF_ND
                       + (wn * 32 + (lane & 7) + ((lane >> 4) << 3)) * ND_STRIDE
                       + (((lane >> 3) & 1) << 4);
    const uint32_t aMK = sb + OFF_MK + (wid * 16 + (lane & 15)) * MK_STRIDE + ((lane >> 4) << 4);
    const uint32_t bYT = sb + OFF_YT
                       + ((lane & 7) + ((lane >> 4) << 3)) * YT_STRIDE
                       + (((lane >> 3) & 1) << 4);

    // ---- staging maps (R8-style, conflict-free) ----
    const int srow  = tid >> 4;               // nodes: rows srow, srow+32 (16 thr/row)
    const int sc16  = tid & 15;
    const int mrow  = tid >> 1;               // mask: 0..255 rows, 2 thr/row
    const int mhalf = tid & 1;                // 32-int half

    uint2    rN[8];                           // nodes rows srow/srow+32, packed bf16
    uint32_t rM[16];                          // mask 32 ints -> 16 bf16x2

    {
        const float* s0 = nodes + (size_t)(z * NC + srow) * DK + sc16 * 4;
        #pragma unroll
        for (int i = 0; i < 4; i++) {
            rN[i]     = pack_bf4(*(const float4*)(s0 + i * 64));
            rN[4 + i] = pack_bf4(*(const float4*)(s0 + 32 * DK + i * 64));
        }
        const int* mp = mask + (size_t)mrow * Nn + z * NC + mhalf * 32;
        #pragma unroll
        for (int j = 0; j < 8; j++) {
            int4 v = *(const int4*)(mp + j * 4);
            rM[2 * j]     = cvtm(v.x, v.y);
            rM[2 * j + 1] = cvtm(v.z, v.w);
        }
    }

    for (int c = z; c < NCHK; c += ZS) {
        // ---- STS nodes + mask from prefetched regs ----
        {
            char* dn = sm + OFF_ND + srow * ND_STRIDE + sc16 * 8;
            #pragma unroll
            for (int i = 0; i < 4; i++) {
                *(uint2*)(dn + i * 128)                  = rN[i];
                *(uint2*)(dn + 32 * ND_STRIDE + i * 128) = rN[4 + i];
            }
            char* dm = sm + OFF_MK + mrow * MK_STRIDE + mhalf * 64;
            *(uint4*)(dm)      = make_uint4(rM[0],  rM[1],  rM[2],  rM[3]);
            *(uint4*)(dm + 16) = make_uint4(rM[4],  rM[5],  rM[6],  rM[7]);
            *(uint4*)(dm + 32) = make_uint4(rM[8],  rM[9],  rM[10], rM[11]);
            *(uint4*)(dm + 48) = make_uint4(rM[12], rM[13], rM[14], rM[15]);
        }
        __syncthreads();   // nodes + mask (+W on iter 0) visible

        // ---- GEMM1: yT = W @ nodes^T  (M=128, N=64, K=256) ----
        float aT[4][4] = {}, aG[4][4] = {};
        #pragma unroll
        for (int ks = 0; ks < 16; ks++) {
            uint32_t At[4], Ag[4], B0[4], B1[4];
            LDSM_X4(At, aWt + ks * 32);
            LDSM_X4(Ag, aWg + ks * 32);
            LDSM_X4(B0, bNd + ks * 32);
            LDSM_X4(B1, bNd + 16 * ND_STRIDE + ks * 32);
            MMA_BF16(aT[0], At, B0[0], B0[1]);
            MMA_BF16(aT[1], At, B0[2], B0[3]);
            MMA_BF16(aT[2], At, B1[0], B1[1]);
            MMA_BF16(aT[3], At, B1[2], B1[3]);
            MMA_BF16(aG[0], Ag, B0[0], B0[1]);
            MMA_BF16(aG[1], Ag, B0[2], B0[3]);
            MMA_BF16(aG[2], Ag, B1[0], B1[1]);
            MMA_BF16(aG[3], Ag, B1[2], B1[3]);
        }

        // ---- epilogue: y = (t+bt)*sigmoid(g+bg) -> yT smem bf16 ----
        {
            char* r0 = sm + OFF_YT + (wm * 16 + g) * YT_STRIDE + (wn * 32 + 2 * tg) * 2;
            char* r1 = r0 + 8 * YT_STRIDE;
            #pragma unroll
            for (int j = 0; j < 4; j++) {
                __nv_bfloat162 h;
                h = __floats2bfloat162_rn((aT[j][0] + bt0) * sigm(aG[j][0] + bg0),
                                          (aT[j][1] + bt0) * sigm(aG[j][1] + bg0));
                *(uint32_t*)(r0 + j * 16) = *reinterpret_cast<uint32_t*>(&h);
                h = __floats2bfloat162_rn((aT[j][2] + bt1) * sigm(aG[j][2] + bg1),
                                          (aT[j][3] + bt1) * sigm(aG[j][3] + bg1));
                *(uint32_t*)(r1 + j * 16) = *reinterpret_cast<uint32_t*>(&h);
            }
        }

        // ---- prefetch chunk c+ZS into regs (hidden under GEMM2) ----
        if (c + ZS < NCHK) {
            const float* s0 = nodes + (size_t)((c + ZS) * NC + srow) * DK + sc16 * 4;
            #pragma unroll
            for (int i = 0; i < 4; i++) {
                rN[i]     = pack_bf4(*(const float4*)(s0 + i * 64));
                rN[4 + i] = pack_bf4(*(const float4*)(s0 + 32 * DK + i * 64));
            }
            const int* mp = mask + (size_t)mrow * Nn + (c + ZS) * NC + mhalf * 32;
            #pragma unroll
            for (int j = 0; j < 8; j++) {
                int4 v = *(const int4*)(mp + j * 4);
                rM[2 * j]     = cvtm(v.x, v.y);
                rM[2 * j + 1] = cvtm(v.z, v.w);
            }
        }
        __syncthreads();   // yT visible

        // ---- GEMM2: acc2 += mask @ yT  (warp 16b x 128d, K=64) ----
        #pragma unroll
        for (int ks = 0; ks < 4; ks++) {
            uint32_t A[4];
            LDSM_X4(A, aMK + ks * 32);
            #pragma unroll
            for (int nf = 0; nf < 8; nf++) {
                uint32_t Y[4];
                LDSM_X4(Y, bYT + nf * 16 * YT_STRIDE + ks * 32);
                MMA_BF16(acc2[2 * nf],     A, Y[0], Y[1]);
                MMA_BF16(acc2[2 * nf + 1], A, Y[2], Y[3]);
            }
        }
        __syncthreads();   // GEMM2 done: nodes/mask/yT smem free
    }

    // ---- drain: atomic-accumulate split-K partials ----
    {
        const int r = wid * 16 + g;
        #pragma unroll
        for (int j = 0; j < 16; j++) {
            const int cb = d0 + j * 8 + 2 * tg;
            atomicAdd(out + (size_t)r * DK + cb,           acc2[j][0]);
            atomicAdd(out + (size_t)r * DK + cb + 1,       acc2[j][1]);
            atomicAdd(out + (size_t)(r + 8) * DK + cb,     acc2[j][2]);
            atomicAdd(out + (size_t)(r + 8) * DK + cb + 1, acc2[j][3]);
        }
    }
}

__global__ void kzero(float* __restrict__ o, int n) {
    const int i = blockIdx.x * 256 + threadIdx.x;
    if (i < n) o[i] = 0.f;
}

extern "C" void kernel_launch(void* const* d_in, const int* in_sizes, int n_in,
                              void* d_out, int out_size)
{
    const float* nodes = (const float*)d_in[0];
    const int*   mask  = (const int*)  d_in[1];
    const float* Wt    = (const float*)d_in[2];
    const float* bt    = (const float*)d_in[3];
    const float* Wg    = (const float*)d_in[4];
    const float* bg    = (const float*)d_in[5];
    float* out = (float*)d_out;

    const int Nn = in_sizes[0] / DK;   // 200000

    cudaFuncSetAttribute(fused_agg, cudaFuncAttributeMaxDynamicSharedMemorySize, SMEM_TOTAL);

    kzero<<<(out_size + 255) / 256, 256>>>(out, out_size);
    fused_agg<<<dim3(ZS, 2), 512, SMEM_TOTAL>>>(nodes, mask, Wt, bt, Wg, bg, out, Nn);
}

// round 14
// speedup vs baseline: 1.5639x; 1.4847x over previous
#include <cuda_runtime.h>
#include <cuda_bf16.h>
#include <cstdint>
#include <cstddef>

#define DK 256        // feature dim
#define NC 32         // nodes per chunk (GEMM2 K)
#define ZS 74         // split-K CTAs per d-tile (x2 d-tiles = 148 CTAs)

// ---- smem layout: W resident; nodes double-buffered; mask/yT single ----
#define W_STRIDE  528                      // 256 bf16 + 8 pad
#define ND_STRIDE 528
#define MK_STRIDE 160                      // 32 int32 + 8 pad
#define YT_STRIDE 80                       // 32 bf16 + 8 pad
#define OFF_WT 0
#define OFF_WG 67584                       // 128*528
#define OFF_ND 135168                      // 2 x (32*528 = 16896)
#define OFF_MK 168960                      // 256*160 = 40960
#define OFF_YT 209920                      // 128*80  = 10240
#define SMEM_TOTAL 220160
#define ND_BUF 16896

static __device__ __forceinline__ uint32_t smem_u32(const void* p) {
    uint32_t a;
    asm("{ .reg .u64 t; cvta.to.shared.u64 t, %1; cvt.u32.u64 %0, t; }" : "=r"(a) : "l"(p));
    return a;
}

#define LDSM_X4(R, addr)                                                      \
    asm volatile("ldmatrix.sync.aligned.m8n8.x4.shared.b16 {%0,%1,%2,%3}, [%4];" \
                 : "=r"((R)[0]), "=r"((R)[1]), "=r"((R)[2]), "=r"((R)[3])     \
                 : "r"(addr))

#define MMA_BF16(C, A, b0, b1)                                                \
    asm volatile("mma.sync.aligned.m16n8k16.row.col.f32.bf16.bf16.f32 "       \
                 "{%0,%1,%2,%3},{%4,%5,%6,%7},{%8,%9},{%0,%1,%2,%3};"         \
                 : "+f"((C)[0]), "+f"((C)[1]), "+f"((C)[2]), "+f"((C)[3])     \
                 : "r"((A)[0]), "r"((A)[1]), "r"((A)[2]), "r"((A)[3]),        \
                   "r"(b0), "r"(b1))

#define CP16(dst, src)                                                        \
    asm volatile("cp.async.cg.shared.global [%0], [%1], 16;"                  \
                 :: "r"(dst), "l"(src) : "memory")
#define CP_COMMIT() asm volatile("cp.async.commit_group;" ::: "memory")
#define CP_WAIT0()  asm volatile("cp.async.wait_group 0;" ::: "memory")

// mask int {0,1} pair -> packed bf16x2 {1.0 or 0.0}: exact, 2 IMADs
static __device__ __forceinline__ uint32_t cvtm(int2 v) {
    return (uint32_t)v.x * 0x3F80u + (uint32_t)v.y * 0x3F800000u;
}

static __device__ __forceinline__ uint2 pack_bf4(float4 v) {
    __nv_bfloat162 lo = __floats2bfloat162_rn(v.x, v.y);
    __nv_bfloat162 hi = __floats2bfloat162_rn(v.z, v.w);
    uint2 u;
    u.x = *reinterpret_cast<uint32_t*>(&lo);
    u.y = *reinterpret_cast<uint32_t*>(&hi);
    return u;
}

static __device__ __forceinline__ float sigm(float x) { return 1.0f / (1.0f + __expf(-x)); }

// ---------------------------------------------------------------------------
// R8 core with 2 barriers/chunk (grid 74 z x 2 d-tiles, 512 thr):
//   STS nodes(c) [buf it&1] ; CP_WAIT | barA |
//   GEMM2(c-1) [mask int smem + yT smem] | barB |
//   cp.async mask(c) ; prefetch rN(c+ZS) ; GEMM1(c) ; epilogue -> yT
// Register profile identical to R8 (acc2 64 + GEMM1 acc 16 + rN 8).
// ---------------------------------------------------------------------------
__global__ __launch_bounds__(512, 1)
void fused_agg(const float* __restrict__ nodes, const int* __restrict__ mask,
               const float* __restrict__ Wt, const float* __restrict__ bt,
               const float* __restrict__ Wg, const float* __restrict__ bg,
               float* __restrict__ out, int Nn)
{
    extern __shared__ char sm[];
    const uint32_t sb = smem_u32(sm);
    const int tid  = threadIdx.x;
    const int lane = tid & 31;
    const int wid  = tid >> 5;
    const int g    = lane >> 2;
    const int tg   = lane & 3;
    const int z    = blockIdx.x;
    const int d0   = blockIdx.y * 128;

    // GEMM1 warp roles: 8 m-warps (16 d rows) x 2 n-warps (16 n cols)
    const int wm = wid & 7;
    const int wn = wid >> 3;

    const float bt0 = bt[d0 + wm * 16 + g];
    const float bt1 = bt[d0 + wm * 16 + 8 + g];
    const float bg0 = bg[d0 + wm * 16 + g];
    const float bg1 = bg[d0 + wm * 16 + 8 + g];

    // Persistent GEMM2 accumulators (warp tile 16b x 128d): 16 n8 x 4 regs
    float acc2[16][4];
    #pragma unroll
    for (int j = 0; j < 16; j++)
        #pragma unroll
        for (int q = 0; q < 4; q++) acc2[j][q] = 0.f;

    const int NCHK = Nn / NC;   // 200000/32 = 6250 exactly

    // ---- stage resident W (both matrices, f32 -> bf16) ----
    #pragma unroll
    for (int i = 0; i < 16; i++) {
        int f4  = tid + i * 512;
        int row = f4 >> 6;
        int col = (f4 & 63) * 4;
        uint2 a = pack_bf4(*(const float4*)(Wt + (size_t)(d0 + row) * DK + col));
        uint2 b = pack_bf4(*(const float4*)(Wg + (size_t)(d0 + row) * DK + col));
        *(uint2*)(sm + OFF_WT + row * W_STRIDE + col * 2) = a;
        *(uint2*)(sm + OFF_WG + row * W_STRIDE + col * 2) = b;
    }

    // ldmatrix lane addresses
    const uint32_t aWt = sb + OFF_WT + (wm * 16 + (lane & 15)) * W_STRIDE + ((lane >> 4) << 4);
    const uint32_t aWg = aWt + (uint32_t)(OFF_WG - OFF_WT);
    const uint32_t bNd = sb + OFF_ND
                       + (wn * 16 + (lane & 7) + ((lane >> 4) << 3)) * ND_STRIDE
                       + (((lane >> 3) & 1) << 4);
    const uint32_t bY  = sb + OFF_YT
                       + ((lane & 7) + ((lane >> 4) << 3)) * YT_STRIDE
                       + (((lane >> 3) & 1) << 4);

    // nodes register staging (packed bf16 at load: 8 regs)
    const int srow = tid >> 4;              // 0..31 rows, 16 thr/row
    const int sc16 = tid & 15;
    uint2 rN[4];
    {
        const float* s0 = nodes + (size_t)(z * NC + srow) * DK + sc16 * 4;
        #pragma unroll
        for (int i = 0; i < 4; i++) rN[i] = pack_bf4(*(const float4*)(s0 + i * 64));
    }

    int it = 0;
    for (int c = z; c < NCHK; c += ZS, ++it) {
        const uint32_t ndb = (uint32_t)(it & 1) * ND_BUF;

        // ---- STS nodes(c) from prefetched packed regs ----
        {
            char* dn = sm + OFF_ND + ndb + srow * ND_STRIDE + sc16 * 8;
            #pragma unroll
            for (int i = 0; i < 4; i++) *(uint2*)(dn + i * 128) = rN[i];
        }
        CP_WAIT0();        // mask(c-1) cp.async (issued last iter) retired
        __syncthreads();   // barA: nodes(c), yT(c-1), mask(c-1) all visible

        // ---- GEMM2(c-1): acc2 += mask(c-1) @ yT(c-1)  (warp 16b x 128d) ----
        if (it > 0) {
            const char* mrow = sm + OFF_MK + (wid * 16 + g) * MK_STRIDE;
            #pragma unroll
            for (int ks = 0; ks < 2; ks++) {
                const int kk = ks * 16;
                uint32_t A[4];
                A[0] = cvtm(*(const int2*)(mrow + (kk + 2 * tg) * 4));
                A[1] = cvtm(*(const int2*)(mrow + 8 * MK_STRIDE + (kk + 2 * tg) * 4));
                A[2] = cvtm(*(const int2*)(mrow + (kk + 8 + 2 * tg) * 4));
                A[3] = cvtm(*(const int2*)(mrow + 8 * MK_STRIDE + (kk + 8 + 2 * tg) * 4));
                #pragma unroll
                for (int nf = 0; nf < 8; nf++) {
                    uint32_t Y[4];
                    LDSM_X4(Y, bY + nf * 16 * YT_STRIDE + ks * 32);
                    MMA_BF16(acc2[2 * nf],     A, Y[0], Y[1]);
                    MMA_BF16(acc2[2 * nf + 1], A, Y[2], Y[3]);
                }
            }
        }
        __syncthreads();   // barB: GEMM2 done -> mask & yT buffers reusable

        // ---- issue cp.async mask(c): consumed by GEMM2(c) next iter ----
        {
            const int n0 = c * NC;
            #pragma unroll
            for (int i = 0; i < 4; i++) {
                int o = tid + i * 512;          // 2048 ops: 256 rows x 8 segs
                int row = o >> 3, seg = o & 7;
                CP16(sb + OFF_MK + row * MK_STRIDE + seg * 16,
                     (const char*)(mask + (size_t)row * Nn + n0) + seg * 16);
            }
            CP_COMMIT();
        }

        // ---- prefetch nodes(c+ZS): hidden under GEMM1 ----
        if (c + ZS < NCHK) {
            const float* s0 = nodes + (size_t)((c + ZS) * NC + srow) * DK + sc16 * 4;
            #pragma unroll
            for (int i = 0; i < 4; i++) rN[i] = pack_bf4(*(const float4*)(s0 + i * 64));
        }

        // ---- GEMM1(c): yT = W @ nodes^T  (M=128, N=32, K=256) ----
        float aT0[4] = {0,0,0,0}, aT1[4] = {0,0,0,0};
        float aG0[4] = {0,0,0,0}, aG1[4] = {0,0,0,0};
        #pragma unroll
        for (int ks = 0; ks < 16; ks++) {
            uint32_t At[4], Ag[4], Bn[4];
            LDSM_X4(At, aWt + ks * 32);
            LDSM_X4(Ag, aWg + ks * 32);
            LDSM_X4(Bn, bNd + ndb + ks * 32);
            MMA_BF16(aT0, At, Bn[0], Bn[1]);
            MMA_BF16(aT1, At, Bn[2], Bn[3]);
            MMA_BF16(aG0, Ag, Bn[0], Bn[1]);
            MMA_BF16(aG1, Ag, Bn[2], Bn[3]);
        }

        // ---- epilogue: y = (t+bt)*sigmoid(g+bg) -> yT smem bf16 ----
        {
            char* r0 = sm + OFF_YT + (wm * 16 + g) * YT_STRIDE + (wn * 16 + 2 * tg) * 2;
            char* r1 = r0 + 8 * YT_STRIDE;
            __nv_bfloat162 h;
            h = __floats2bfloat162_rn((aT0[0] + bt0) * sigm(aG0[0] + bg0),
                                      (aT0[1] + bt0) * sigm(aG0[1] + bg0));
            *(uint32_t*)r0 = *reinterpret_cast<uint32_t*>(&h);
            h = __floats2bfloat162_rn((aT0[2] + bt1) * sigm(aG0[2] + bg1),
                                      (aT0[3] + bt1) * sigm(aG0[3] + bg1));
            *(uint32_t*)r1 = *reinterpret_cast<uint32_t*>(&h);
            h = __floats2bfloat162_rn((aT1[0] + bt0) * sigm(aG1[0] + bg0),
                                      (aT1[1] + bt0) * sigm(aG1[1] + bg0));
            *(uint32_t*)(r0 + 16) = *reinterpret_cast<uint32_t*>(&h);
            h = __floats2bfloat162_rn((aT1[2] + bt1) * sigm(aG1[2] + bg1),
                                      (aT1[3] + bt1) * sigm(aG1[3] + bg1));
            *(uint32_t*)(r1 + 16) = *reinterpret_cast<uint32_t*>(&h);
        }
        // no trailing barrier: next iter's STS targets the other nd buffer;
        // yT/mask overwrites are fenced by next iter's barA+GEMM2+barB.
    }

    // ---- tail: GEMM2 for the last produced chunk ----
    if (it > 0) {
        CP_WAIT0();
        __syncthreads();
        const char* mrow = sm + OFF_MK + (wid * 16 + g) * MK_STRIDE;
        #pragma unroll
        for (int ks = 0; ks < 2; ks++) {
            const int kk = ks * 16;
            uint32_t A[4];
            A[0] = cvtm(*(const int2*)(mrow + (kk + 2 * tg) * 4));
            A[1] = cvtm(*(const int2*)(mrow + 8 * MK_STRIDE + (kk + 2 * tg) * 4));
            A[2] = cvtm(*(const int2*)(mrow + (kk + 8 + 2 * tg) * 4));
            A[3] = cvtm(*(const int2*)(mrow + 8 * MK_STRIDE + (kk + 8 + 2 * tg) * 4));
            #pragma unroll
            for (int nf = 0; nf < 8; nf++) {
                uint32_t Y[4];
                LDSM_X4(Y, bY + nf * 16 * YT_STRIDE + ks * 32);
                MMA_BF16(acc2[2 * nf],     A, Y[0], Y[1]);
                MMA_BF16(acc2[2 * nf + 1], A, Y[2], Y[3]);
            }
        }
    }

    // ---- drain: atomic-accumulate split-K partials ----
    {
        const int r = wid * 16 + g;
        #pragma unroll
        for (int j = 0; j < 16; j++) {
            const int cb = d0 + j * 8 + 2 * tg;
            atomicAdd(out + (size_t)r * DK + cb,           acc2[j][0]);
            atomicAdd(out + (size_t)r * DK + cb + 1,       acc2[j][1]);
            atomicAdd(out + (size_t)(r + 8) * DK + cb,     acc2[j][2]);
            atomicAdd(out + (size_t)(r + 8) * DK + cb + 1, acc2[j][3]);
        }
    }
}

__global__ void kzero(float* __restrict__ o, int n) {
    const int i = blockIdx.x * 256 + threadIdx.x;
    if (i < n) o[i] = 0.f;
}

extern "C" void kernel_launch(void* const* d_in, const int* in_sizes, int n_in,
                              void* d_out, int out_size)
{
    const float* nodes = (const float*)d_in[0];
    const int*   mask  = (const int*)  d_in[1];
    const float* Wt    = (const float*)d_in[2];
    const float* bt    = (const float*)d_in[3];
    const float* Wg    = (const float*)d_in[4];
    const float* bg    = (const float*)d_in[5];
    float* out = (float*)d_out;

    const int Nn = in_sizes[0] / DK;   // 200000

    cudaFuncSetAttribute(fused_agg, cudaFuncAttributeMaxDynamicSharedMemorySize, SMEM_TOTAL);

    kzero<<<(out_size + 255) / 256, 256>>>(out, out_size);
    fused_agg<<<dim3(ZS, 2), 512, SMEM_TOTAL>>>(nodes, mask, Wt, bt, Wg, bg, out, Nn);
}